// round 7
// baseline (speedup 1.0000x reference)
#include <cuda_runtime.h>
#include <cuda_bf16.h>
#include <math.h>
#include <stdint.h>

#define AR 8192
#define ED 1024
#define MD 1024

// ---------------- device scratch ----------------
__device__ __nv_bfloat16 g_p1[(size_t)AR * MD];
__device__ __nv_bfloat16 g_p2[(size_t)AR * MD];
__device__ float g_s1[MD];
__device__ float g_s2[MD];
__device__ float g_bias1[MD];
__device__ float g_bias2[MD];
__device__ float g_logits[2 * AR];
__device__ float g_wexp[2 * AR];

__device__ __forceinline__ float elu1(float x) { return x > 0.0f ? x : expm1f(x); }

__device__ __forceinline__ uint32_t smem_u32(const void* p) {
    uint32_t a;
    asm("{ .reg .u64 t; cvta.to.shared.u64 t, %1; cvt.u32.u64 %0, t; }" : "=r"(a) : "l"(p));
    return a;
}
#define LDMATRIX_X4(r0, r1, r2, r3, addr) \
    asm volatile("ldmatrix.sync.aligned.m8n8.x4.shared.b16 {%0,%1,%2,%3}, [%4];" \
        : "=r"(r0), "=r"(r1), "=r"(r2), "=r"(r3) : "r"(addr))
#define MMA16816(c0, c1, c2, c3, a0, a1, a2, a3, b0, b1) \
    asm volatile("mma.sync.aligned.m16n8k16.row.col.f32.bf16.bf16.f32 " \
        "{%0,%1,%2,%3}, {%4,%5,%6,%7}, {%8,%9}, {%0,%1,%2,%3};" \
        : "+f"(c0), "+f"(c1), "+f"(c2), "+f"(c3) \
        : "r"(a0), "r"(a1), "r"(a2), "r"(a3), "r"(b0), "r"(b1))
#define STS128(addr, r0, r1, r2, r3) \
    asm volatile("st.shared.v4.b32 [%0], {%1,%2,%3,%4};" \
        :: "r"(addr), "r"(r0), "r"(r1), "r"(r2), "r"(r3))

// ---------------- zero + ctx GEMV fused ----------------
__global__ void zeroctx_kernel(const float* __restrict__ ctx,
                               const float* __restrict__ Wc1, const float* __restrict__ Wc2,
                               const float* __restrict__ b1, const float* __restrict__ b2,
                               float* __restrict__ out) {
    int gid = blockIdx.x * blockDim.x + threadIdx.x;
    if (gid < MD) { g_s1[gid] = 0.0f; g_s2[gid] = 0.0f; }
    if (gid < 2 * ED) out[gid] = 0.0f;

    int g = gid >> 5;
    int lane = gid & 31;
    int mat = g >> 10, row = g & 1023;
    const float* W = mat ? Wc2 : Wc1;
    const float* b = mat ? b2 : b1;
    float* o = mat ? g_bias2 : g_bias1;
    float acc = 0.0f;
    const float* wr = W + (size_t)row * ED;
    for (int k = lane; k < ED; k += 32) acc += wr[k] * ctx[k];
    #pragma unroll
    for (int off = 16; off > 0; off >>= 1) acc += __shfl_down_sync(0xffffffffu, acc, off);
    if (lane == 0) o[row] = b[row] + acc;
}

// ---------------- bf16 mma.sync GEMM with in-loader f32->bf16 conversion ---
// P = elu(A @ W^T + bias), A/W read as f32, converted during smem fill.
// CTA 128x128, BK=64, 2-stage, 2 CTAs/SM, 8 warps 2(M)x4(N) -> 64x32 tiles.
// blockIdx.z selects matrix. Fused column-sum epilogue.
#define BK 64
#define NCHUNK (ED / BK)                 // 16
#define STAGE_BYTES (2 * 128 * 128)      // A 16KB + B 16KB

__global__ void __launch_bounds__(256, 2)
gemm_mma_kernel(const float* __restrict__ Af1, const float* __restrict__ Wf1,
                const float* __restrict__ bias1v, __nv_bfloat16* __restrict__ P1,
                float* __restrict__ S1,
                const float* __restrict__ Af2, const float* __restrict__ Wf2,
                const float* __restrict__ bias2v, __nv_bfloat16* __restrict__ P2,
                float* __restrict__ S2) {
    extern __shared__ __align__(128) char dyn[];
    __shared__ float bias_s[128];

    const int z = blockIdx.z;
    const float* Af = z ? Af2 : Af1;
    const float* Wf = z ? Wf2 : Wf1;
    const float* bias = z ? bias2v : bias1v;
    __nv_bfloat16* P = z ? P2 : P1;
    float* S = z ? S2 : S1;

    const int tid = threadIdx.x;
    const int wid = tid >> 5, lane = tid & 31;
    const int rowBlock = blockIdx.y * 128;
    const int colBlock = blockIdx.x * 128;

    uint32_t sbase = (smem_u32(dyn) + 127u) & ~127u;

    if (tid < 128) bias_s[tid] = bias[colBlock + tid];

    const int m0 = (wid & 1) * 64;
    const int n0 = (wid >> 1) * 32;

    float acc[4][4][4];
    #pragma unroll
    for (int i = 0; i < 4; i++)
        #pragma unroll
        for (int j = 0; j < 4; j++)
            #pragma unroll
            for (int q = 0; q < 4; q++) acc[i][j][q] = 0.0f;

    // loader: per thread 8 segments (A:4, W:4); each = 8 f32 -> 8 bf16 (16B STS)
    auto load_chunk = [&](int chunk, int stage) {
        const int k0 = chunk * BK;
        uint32_t ab = sbase + stage * STAGE_BYTES;
        uint32_t bb = ab + 16384;
        #pragma unroll
        for (int l = 0; l < 8; l++) {
            int i = tid + l * 256;               // 0..2047
            const float* src;
            uint32_t dst;
            if (l < 4) {
                int r = i >> 3, c = i & 7;
                dst = ab + (uint32_t)(r * 128) + (uint32_t)((c ^ (r & 7)) << 4);
                src = Af + (size_t)(rowBlock + r) * ED + k0 + c * 8;
            } else {
                int j = i - 1024;
                int r = j >> 3, c = j & 7;
                dst = bb + (uint32_t)(r * 128) + (uint32_t)((c ^ (r & 7)) << 4);
                src = Wf + (size_t)(colBlock + r) * ED + k0 + c * 8;
            }
            float4 v0 = *(const float4*)src;
            float4 v1 = *(const float4*)(src + 4);
            uint32_t q0, q1, q2, q3;
            asm("cvt.rn.bf16x2.f32 %0, %1, %2;" : "=r"(q0) : "f"(v0.y), "f"(v0.x));
            asm("cvt.rn.bf16x2.f32 %0, %1, %2;" : "=r"(q1) : "f"(v0.w), "f"(v0.z));
            asm("cvt.rn.bf16x2.f32 %0, %1, %2;" : "=r"(q2) : "f"(v1.y), "f"(v1.x));
            asm("cvt.rn.bf16x2.f32 %0, %1, %2;" : "=r"(q3) : "f"(v1.w), "f"(v1.z));
            STS128(dst, q0, q1, q2, q3);
        }
    };

    load_chunk(0, 0);
    __syncthreads();

    const int lr = lane & 7, sub = lane >> 3;
    int arow[4], brow[2];
    uint32_t aswz[4], bswz[2];
    #pragma unroll
    for (int mi = 0; mi < 4; mi++) {
        int r = m0 + mi * 16 + ((sub & 1) << 3) + lr;
        arow[mi] = r * 128; aswz[mi] = (uint32_t)(r & 7);
    }
    const uint32_t achunkbit = (uint32_t)(sub >> 1);
    #pragma unroll
    for (int p = 0; p < 2; p++) {
        int r = n0 + p * 16 + ((sub >> 1) << 3) + lr;
        brow[p] = r * 128; bswz[p] = (uint32_t)(r & 7);
    }
    const uint32_t bchunkbit = (uint32_t)(sub & 1);

    for (int ch = 0; ch < NCHUNK; ch++) {
        const int s = ch & 1;
        // issue next chunk's loads first (LDG latency overlaps this chunk's MMAs)
        if (ch + 1 < NCHUNK) load_chunk(ch + 1, s ^ 1);

        uint32_t ab = sbase + s * STAGE_BYTES;
        uint32_t bb = ab + 16384;
        #pragma unroll
        for (int ks = 0; ks < 4; ks++) {
            uint32_t a[4][4], b[8];
            #pragma unroll
            for (int mi = 0; mi < 4; mi++) {
                uint32_t addr = ab + (uint32_t)arow[mi] +
                                ((((uint32_t)(ks << 1) | achunkbit) ^ aswz[mi]) << 4);
                LDMATRIX_X4(a[mi][0], a[mi][1], a[mi][2], a[mi][3], addr);
            }
            #pragma unroll
            for (int p = 0; p < 2; p++) {
                uint32_t addr = bb + (uint32_t)brow[p] +
                                ((((uint32_t)(ks << 1) | bchunkbit) ^ bswz[p]) << 4);
                LDMATRIX_X4(b[p * 4 + 0], b[p * 4 + 1], b[p * 4 + 2], b[p * 4 + 3], addr);
            }
            #pragma unroll
            for (int mi = 0; mi < 4; mi++)
                #pragma unroll
                for (int nt = 0; nt < 4; nt++)
                    MMA16816(acc[mi][nt][0], acc[mi][nt][1], acc[mi][nt][2], acc[mi][nt][3],
                             a[mi][0], a[mi][1], a[mi][2], a[mi][3],
                             b[nt * 2], b[nt * 2 + 1]);
        }
        __syncthreads();
    }

    // epilogue: bias + elu -> bf16 stores, fused column sums
    const int qrow = lane >> 2;
    const int qcol = (lane & 3) * 2;
    float csum[4][2];
    #pragma unroll
    for (int nt = 0; nt < 4; nt++) { csum[nt][0] = 0.0f; csum[nt][1] = 0.0f; }

    #pragma unroll
    for (int mi = 0; mi < 4; mi++) {
        #pragma unroll
        for (int nt = 0; nt < 4; nt++) {
            int col = n0 + nt * 8 + qcol;
            float bv0 = bias_s[col], bv1 = bias_s[col + 1];
            int r0 = rowBlock + m0 + mi * 16 + qrow;
            float x0 = elu1(acc[mi][nt][0] + bv0);
            float x1 = elu1(acc[mi][nt][1] + bv1);
            float x2 = elu1(acc[mi][nt][2] + bv0);
            float x3 = elu1(acc[mi][nt][3] + bv1);
            csum[nt][0] += x0 + x2;
            csum[nt][1] += x1 + x3;
            uint32_t p01, p23;
            asm("cvt.rn.bf16x2.f32 %0, %1, %2;" : "=r"(p01) : "f"(x1), "f"(x0));
            asm("cvt.rn.bf16x2.f32 %0, %1, %2;" : "=r"(p23) : "f"(x3), "f"(x2));
            *(uint32_t*)(P + (size_t)r0 * MD + colBlock + col) = p01;
            *(uint32_t*)(P + (size_t)(r0 + 8) * MD + colBlock + col) = p23;
        }
    }
    #pragma unroll
    for (int nt = 0; nt < 4; nt++) {
        #pragma unroll
        for (int q = 0; q < 2; q++) {
            float v = csum[nt][q];
            v += __shfl_xor_sync(0xffffffffu, v, 4);
            v += __shfl_xor_sync(0xffffffffu, v, 8);
            v += __shfl_xor_sync(0xffffffffu, v, 16);
            if (lane < 4) atomicAdd(&S[colBlock + n0 + nt * 8 + qcol + q], v);
        }
    }
}

// ---------------- logits GEMV ----------------
__global__ void logits_kernel() {
    __shared__ float s[MD];
    int mat = blockIdx.x >> 10;
    const uint32_t* P = (const uint32_t*)(mat ? g_p2 : g_p1);
    const float* S = mat ? g_s1 : g_s2;
    float* L = g_logits + mat * AR;

    for (int i = threadIdx.x; i < MD; i += blockDim.x) s[i] = S[i];
    __syncthreads();

    int wid = threadIdx.x >> 5, lane = threadIdx.x & 31;
    int row = (blockIdx.x & 1023) * 8 + wid;
    const uint32_t* p = P + (size_t)row * 512;
    float acc = 0.0f;
    #pragma unroll 4
    for (int k = lane; k < 512; k += 32) {
        uint32_t u = p[k];
        __nv_bfloat162 h = *(__nv_bfloat162*)&u;
        acc += __bfloat162float(h.x) * s[2 * k] + __bfloat162float(h.y) * s[2 * k + 1];
    }
    #pragma unroll
    for (int o = 16; o > 0; o >>= 1) acc += __shfl_down_sync(0xffffffffu, acc, o);
    if (lane == 0) L[row] = acc;
}

// ---------------- softmax ----------------
__global__ void softmax_kernel() {
    __shared__ float red[1024];
    int mat = blockIdx.x;
    const float* L = g_logits + mat * AR;
    float* W = g_wexp + mat * AR;
    int t = threadIdx.x;
    float m = -INFINITY;
    for (int i = t; i < AR; i += 1024) m = fmaxf(m, L[i]);
    red[t] = m; __syncthreads();
    for (int o = 512; o > 0; o >>= 1) { if (t < o) red[t] = fmaxf(red[t], red[t + o]); __syncthreads(); }
    m = red[0]; __syncthreads();
    float z = 0.0f;
    for (int i = t; i < AR; i += 1024) z += expf(L[i] - m);
    red[t] = z; __syncthreads();
    for (int o = 512; o > 0; o >>= 1) { if (t < o) red[t] += red[t + o]; __syncthreads(); }
    float inv = 1.0f / red[0];
    for (int i = t; i < AR; i += 1024) W[i] = expf(L[i] - m) * inv;
}

// ---------------- att = seq.T @ w ----------------
__global__ void att_kernel(const float* __restrict__ seq1, const float* __restrict__ seq2,
                           float* __restrict__ out) {
    int mat = blockIdx.z;
    const float* Sq = mat ? seq2 : seq1;
    const float* W = g_wexp + mat * AR;
    int c = blockIdx.x * 256 + threadIdx.x;
    int r0 = blockIdx.y * 512;
    float acc0 = 0.0f, acc1 = 0.0f;
    #pragma unroll 4
    for (int r = r0; r < r0 + 512; r += 2) {
        acc0 += Sq[(size_t)r * ED + c] * W[r];
        acc1 += Sq[(size_t)(r + 1) * ED + c] * W[r + 1];
    }
    atomicAdd(&out[mat * ED + c], acc0 + acc1);
}

// ---------------- launch ----------------
extern "C" void kernel_launch(void* const* d_in, const int* in_sizes, int n_in,
                              void* d_out, int out_size) {
    const float* seq1 = (const float*)d_in[0];
    const float* seq2 = (const float*)d_in[1];
    const float* ctx  = (const float*)d_in[2];
    const float* Wc1  = (const float*)d_in[3];
    const float* Wc2  = (const float*)d_in[4];
    const float* W1   = (const float*)d_in[5];
    const float* b1   = (const float*)d_in[6];
    const float* W2   = (const float*)d_in[7];
    const float* b2   = (const float*)d_in[8];
    float* out = (float*)d_out;

    __nv_bfloat16 *p1, *p2;
    float *bias1, *bias2, *s1, *s2;
    cudaGetSymbolAddress((void**)&p1, g_p1);
    cudaGetSymbolAddress((void**)&p2, g_p2);
    cudaGetSymbolAddress((void**)&bias1, g_bias1);
    cudaGetSymbolAddress((void**)&bias2, g_bias2);
    cudaGetSymbolAddress((void**)&s1, g_s1);
    cudaGetSymbolAddress((void**)&s2, g_s2);

    size_t smem = 2 * STAGE_BYTES + 128;
    cudaFuncSetAttribute(gemm_mma_kernel, cudaFuncAttributeMaxDynamicSharedMemorySize, (int)smem);

    zeroctx_kernel<<<256, 256>>>(ctx, Wc1, Wc2, b1, b2, out);

    dim3 ggrid(MD / 128, AR / 128, 2);   // (8, 64, 2) = 1024 CTAs
    gemm_mma_kernel<<<ggrid, 256, smem>>>(seq1, W1, bias1, p1, s1,
                                          seq2, W2, bias2, p2, s2);

    logits_kernel<<<2048, 256>>>();
    softmax_kernel<<<2, 1024>>>();
    att_kernel<<<dim3(ED / 256, AR / 512, 2), 256>>>(seq1, seq2, out);
}

// round 8
// speedup vs baseline: 1.3913x; 1.3913x over previous
#include <cuda_runtime.h>
#include <cuda_bf16.h>
#include <math.h>
#include <stdint.h>

#define AR 8192
#define ED 1024
#define MD 1024

// ---------------- device scratch ----------------
__device__ __nv_bfloat16 g_a1[(size_t)AR * ED];
__device__ __nv_bfloat16 g_a2[(size_t)AR * ED];
__device__ __nv_bfloat16 g_wb1[(size_t)MD * ED];
__device__ __nv_bfloat16 g_wb2[(size_t)MD * ED];
__device__ __nv_bfloat16 g_p1[(size_t)AR * MD];
__device__ __nv_bfloat16 g_p2[(size_t)AR * MD];
__device__ float g_s1[MD];
__device__ float g_s2[MD];
__device__ float g_bias1[MD];
__device__ float g_bias2[MD];
__device__ float g_logits[2 * AR];
__device__ float g_wexp[2 * AR];

__device__ __forceinline__ float elu1(float x) { return x > 0.0f ? x : expm1f(x); }

__device__ __forceinline__ uint32_t smem_u32(const void* p) {
    uint32_t a;
    asm("{ .reg .u64 t; cvta.to.shared.u64 t, %1; cvt.u32.u64 %0, t; }" : "=r"(a) : "l"(p));
    return a;
}
#define CP_ASYNC16(dst, src) \
    asm volatile("cp.async.cg.shared.global [%0], [%1], 16;" :: "r"(dst), "l"(src))
#define CP_COMMIT() asm volatile("cp.async.commit_group;" ::: "memory")
#define CP_WAIT1()  asm volatile("cp.async.wait_group 1;" ::: "memory")
#define LDMATRIX_X4(r0, r1, r2, r3, addr) \
    asm volatile("ldmatrix.sync.aligned.m8n8.x4.shared.b16 {%0,%1,%2,%3}, [%4];" \
        : "=r"(r0), "=r"(r1), "=r"(r2), "=r"(r3) : "r"(addr))
#define MMA16816(c0, c1, c2, c3, a0, a1, a2, a3, b0, b1) \
    asm volatile("mma.sync.aligned.m16n8k16.row.col.f32.bf16.bf16.f32 " \
        "{%0,%1,%2,%3}, {%4,%5,%6,%7}, {%8,%9}, {%0,%1,%2,%3};" \
        : "+f"(c0), "+f"(c1), "+f"(c2), "+f"(c3) \
        : "r"(a0), "r"(a1), "r"(a2), "r"(a3), "r"(b0), "r"(b1))

// ---------------- merged conv: all 4 tensors f32 -> bf16 ----------------
#define SEQ_F4 (AR * ED / 4)     // 2097152
#define W_F4   (MD * ED / 4)     // 262144
#define TOT_F4 (2 * SEQ_F4 + 2 * W_F4)

__global__ void conv_all_kernel(const float* __restrict__ seq1, const float* __restrict__ seq2,
                                const float* __restrict__ W1, const float* __restrict__ W2) {
    int i = blockIdx.x * blockDim.x + threadIdx.x;
    if (i >= TOT_F4) return;
    const float* src;
    __nv_bfloat16* dst;
    int off;
    if (i < SEQ_F4)                { src = seq1; dst = g_a1;  off = i; }
    else if (i < 2 * SEQ_F4)       { src = seq2; dst = g_a2;  off = i - SEQ_F4; }
    else if (i < 2 * SEQ_F4 + W_F4){ src = W1;   dst = g_wb1; off = i - 2 * SEQ_F4; }
    else                           { src = W2;   dst = g_wb2; off = i - 2 * SEQ_F4 - W_F4; }
    float4 v = ((const float4*)src)[off];
    uint32_t lo, hi;
    asm("cvt.rn.bf16x2.f32 %0, %1, %2;" : "=r"(lo) : "f"(v.y), "f"(v.x));
    asm("cvt.rn.bf16x2.f32 %0, %1, %2;" : "=r"(hi) : "f"(v.w), "f"(v.z));
    ((uint2*)dst)[off] = make_uint2(lo, hi);
}

// ---------------- zero + ctx GEMV fused ----------------
__global__ void zeroctx_kernel(const float* __restrict__ ctx,
                               const float* __restrict__ Wc1, const float* __restrict__ Wc2,
                               const float* __restrict__ b1, const float* __restrict__ b2,
                               float* __restrict__ out) {
    int gid = blockIdx.x * blockDim.x + threadIdx.x;
    if (gid < MD) { g_s1[gid] = 0.0f; g_s2[gid] = 0.0f; }
    if (gid < 2 * ED) out[gid] = 0.0f;

    int g = gid >> 5;
    int lane = gid & 31;
    int mat = g >> 10, row = g & 1023;
    const float* W = mat ? Wc2 : Wc1;
    const float* b = mat ? b2 : b1;
    float* o = mat ? g_bias2 : g_bias1;
    float acc = 0.0f;
    const float* wr = W + (size_t)row * ED;
    for (int k = lane; k < ED; k += 32) acc += wr[k] * ctx[k];
    #pragma unroll
    for (int off = 16; off > 0; off >>= 1) acc += __shfl_down_sync(0xffffffffu, acc, off);
    if (lane == 0) o[row] = b[row] + acc;
}

// ---------------- bf16 mma.sync GEMM (R3 core): P = elu(A @ W^T + bias) ----
// CTA 128x128, BK=64, 2-stage cp.async, 2 CTAs/SM, warps 2(M)x4(N) 64x32.
// blockIdx.z selects matrix; fused column-sum epilogue.
#define BK 64
#define NCHUNK (ED / BK)                 // 16
#define STAGE_BYTES (2 * 128 * 128)      // A 16KB + B 16KB

__global__ void __launch_bounds__(256, 2)
gemm_mma_kernel(const __nv_bfloat16* __restrict__ A1, const __nv_bfloat16* __restrict__ B1,
                const float* __restrict__ bias1v, __nv_bfloat16* __restrict__ P1,
                float* __restrict__ S1,
                const __nv_bfloat16* __restrict__ A2, const __nv_bfloat16* __restrict__ B2,
                const float* __restrict__ bias2v, __nv_bfloat16* __restrict__ P2,
                float* __restrict__ S2) {
    extern __shared__ __align__(128) char dyn[];
    __shared__ float bias_s[128];

    const int z = blockIdx.z;
    const __nv_bfloat16* A = z ? A2 : A1;
    const __nv_bfloat16* W = z ? B2 : B1;
    const float* bias = z ? bias2v : bias1v;
    __nv_bfloat16* P = z ? P2 : P1;
    float* S = z ? S2 : S1;

    const int tid = threadIdx.x;
    const int wid = tid >> 5, lane = tid & 31;
    const int rowBlock = blockIdx.y * 128;
    const int colBlock = blockIdx.x * 128;

    uint32_t sbase = (smem_u32(dyn) + 127u) & ~127u;

    if (tid < 128) bias_s[tid] = bias[colBlock + tid];

    const int m0 = (wid & 1) * 64;
    const int n0 = (wid >> 1) * 32;

    float acc[4][4][4];
    #pragma unroll
    for (int i = 0; i < 4; i++)
        #pragma unroll
        for (int j = 0; j < 4; j++)
            #pragma unroll
            for (int q = 0; q < 4; q++) acc[i][j][q] = 0.0f;

    auto load_chunk = [&](int chunk, int stage) {
        const int k0 = chunk * BK;
        uint32_t ab = sbase + stage * STAGE_BYTES;
        uint32_t bb = ab + 16384;
        #pragma unroll
        for (int l = 0; l < 4; l++) {
            int i = tid + l * 256;
            int r = i >> 3, c = i & 7;
            uint32_t dst = ab + (uint32_t)(r * 128) + (uint32_t)((c ^ (r & 7)) << 4);
            CP_ASYNC16(dst, A + (size_t)(rowBlock + r) * ED + k0 + c * 8);
        }
        #pragma unroll
        for (int l = 0; l < 4; l++) {
            int i = tid + l * 256;
            int r = i >> 3, c = i & 7;
            uint32_t dst = bb + (uint32_t)(r * 128) + (uint32_t)((c ^ (r & 7)) << 4);
            CP_ASYNC16(dst, W + (size_t)(colBlock + r) * ED + k0 + c * 8);
        }
        CP_COMMIT();
    };

    load_chunk(0, 0);
    load_chunk(1, 1);

    const int lr = lane & 7, sub = lane >> 3;
    int arow[4], brow[2];
    uint32_t aswz[4], bswz[2];
    #pragma unroll
    for (int mi = 0; mi < 4; mi++) {
        int r = m0 + mi * 16 + ((sub & 1) << 3) + lr;
        arow[mi] = r * 128; aswz[mi] = (uint32_t)(r & 7);
    }
    const uint32_t achunkbit = (uint32_t)(sub >> 1);
    #pragma unroll
    for (int p = 0; p < 2; p++) {
        int r = n0 + p * 16 + ((sub >> 1) << 3) + lr;
        brow[p] = r * 128; bswz[p] = (uint32_t)(r & 7);
    }
    const uint32_t bchunkbit = (uint32_t)(sub & 1);

    for (int ch = 0; ch < NCHUNK; ch++) {
        const int s = ch & 1;
        CP_WAIT1();
        __syncthreads();
        uint32_t ab = sbase + s * STAGE_BYTES;
        uint32_t bb = ab + 16384;

        #pragma unroll
        for (int ks = 0; ks < 4; ks++) {
            uint32_t a[4][4], b[8];
            #pragma unroll
            for (int mi = 0; mi < 4; mi++) {
                uint32_t addr = ab + (uint32_t)arow[mi] +
                                ((((uint32_t)(ks << 1) | achunkbit) ^ aswz[mi]) << 4);
                LDMATRIX_X4(a[mi][0], a[mi][1], a[mi][2], a[mi][3], addr);
            }
            #pragma unroll
            for (int p = 0; p < 2; p++) {
                uint32_t addr = bb + (uint32_t)brow[p] +
                                ((((uint32_t)(ks << 1) | bchunkbit) ^ bswz[p]) << 4);
                LDMATRIX_X4(b[p * 4 + 0], b[p * 4 + 1], b[p * 4 + 2], b[p * 4 + 3], addr);
            }
            #pragma unroll
            for (int mi = 0; mi < 4; mi++)
                #pragma unroll
                for (int nt = 0; nt < 4; nt++)
                    MMA16816(acc[mi][nt][0], acc[mi][nt][1], acc[mi][nt][2], acc[mi][nt][3],
                             a[mi][0], a[mi][1], a[mi][2], a[mi][3],
                             b[nt * 2], b[nt * 2 + 1]);
        }
        __syncthreads();
        if (ch < NCHUNK - 2) load_chunk(ch + 2, s);
        else CP_COMMIT();
    }

    // epilogue: bias + elu -> bf16 stores, fused column sums
    const int qrow = lane >> 2;
    const int qcol = (lane & 3) * 2;
    float csum[4][2];
    #pragma unroll
    for (int nt = 0; nt < 4; nt++) { csum[nt][0] = 0.0f; csum[nt][1] = 0.0f; }

    #pragma unroll
    for (int mi = 0; mi < 4; mi++) {
        #pragma unroll
        for (int nt = 0; nt < 4; nt++) {
            int col = n0 + nt * 8 + qcol;
            float bv0 = bias_s[col], bv1 = bias_s[col + 1];
            int r0 = rowBlock + m0 + mi * 16 + qrow;
            float x0 = elu1(acc[mi][nt][0] + bv0);
            float x1 = elu1(acc[mi][nt][1] + bv1);
            float x2 = elu1(acc[mi][nt][2] + bv0);
            float x3 = elu1(acc[mi][nt][3] + bv1);
            csum[nt][0] += x0 + x2;
            csum[nt][1] += x1 + x3;
            uint32_t p01, p23;
            asm("cvt.rn.bf16x2.f32 %0, %1, %2;" : "=r"(p01) : "f"(x1), "f"(x0));
            asm("cvt.rn.bf16x2.f32 %0, %1, %2;" : "=r"(p23) : "f"(x3), "f"(x2));
            *(uint32_t*)(P + (size_t)r0 * MD + colBlock + col) = p01;
            *(uint32_t*)(P + (size_t)(r0 + 8) * MD + colBlock + col) = p23;
        }
    }
    #pragma unroll
    for (int nt = 0; nt < 4; nt++) {
        #pragma unroll
        for (int q = 0; q < 2; q++) {
            float v = csum[nt][q];
            v += __shfl_xor_sync(0xffffffffu, v, 4);
            v += __shfl_xor_sync(0xffffffffu, v, 8);
            v += __shfl_xor_sync(0xffffffffu, v, 16);
            if (lane < 4) atomicAdd(&S[colBlock + n0 + nt * 8 + qcol + q], v);
        }
    }
}

// ---------------- logits GEMV ----------------
__global__ void logits_kernel() {
    __shared__ float s[MD];
    int mat = blockIdx.x >> 10;
    const uint32_t* P = (const uint32_t*)(mat ? g_p2 : g_p1);
    const float* S = mat ? g_s1 : g_s2;
    float* L = g_logits + mat * AR;

    for (int i = threadIdx.x; i < MD; i += blockDim.x) s[i] = S[i];
    __syncthreads();

    int wid = threadIdx.x >> 5, lane = threadIdx.x & 31;
    int row = (blockIdx.x & 1023) * 8 + wid;
    const uint32_t* p = P + (size_t)row * 512;
    float acc = 0.0f;
    #pragma unroll 4
    for (int k = lane; k < 512; k += 32) {
        uint32_t u = p[k];
        __nv_bfloat162 h = *(__nv_bfloat162*)&u;
        acc += __bfloat162float(h.x) * s[2 * k] + __bfloat162float(h.y) * s[2 * k + 1];
    }
    #pragma unroll
    for (int o = 16; o > 0; o >>= 1) acc += __shfl_down_sync(0xffffffffu, acc, o);
    if (lane == 0) L[row] = acc;
}

// ---------------- softmax ----------------
__global__ void softmax_kernel() {
    __shared__ float red[1024];
    int mat = blockIdx.x;
    const float* L = g_logits + mat * AR;
    float* W = g_wexp + mat * AR;
    int t = threadIdx.x;
    float m = -INFINITY;
    for (int i = t; i < AR; i += 1024) m = fmaxf(m, L[i]);
    red[t] = m; __syncthreads();
    for (int o = 512; o > 0; o >>= 1) { if (t < o) red[t] = fmaxf(red[t], red[t + o]); __syncthreads(); }
    m = red[0]; __syncthreads();
    float z = 0.0f;
    for (int i = t; i < AR; i += 1024) z += expf(L[i] - m);
    red[t] = z; __syncthreads();
    for (int o = 512; o > 0; o >>= 1) { if (t < o) red[t] += red[t + o]; __syncthreads(); }
    float inv = 1.0f / red[0];
    for (int i = t; i < AR; i += 1024) W[i] = expf(L[i] - m) * inv;
}

// ---------------- att = seq.T @ w ----------------
__global__ void att_kernel(const float* __restrict__ seq1, const float* __restrict__ seq2,
                           float* __restrict__ out) {
    int mat = blockIdx.z;
    const float* Sq = mat ? seq2 : seq1;
    const float* W = g_wexp + mat * AR;
    int c = blockIdx.x * 256 + threadIdx.x;
    int r0 = blockIdx.y * 512;
    float acc0 = 0.0f, acc1 = 0.0f;
    #pragma unroll 4
    for (int r = r0; r < r0 + 512; r += 2) {
        acc0 += Sq[(size_t)r * ED + c] * W[r];
        acc1 += Sq[(size_t)(r + 1) * ED + c] * W[r + 1];
    }
    atomicAdd(&out[mat * ED + c], acc0 + acc1);
}

// ---------------- launch ----------------
extern "C" void kernel_launch(void* const* d_in, const int* in_sizes, int n_in,
                              void* d_out, int out_size) {
    const float* seq1 = (const float*)d_in[0];
    const float* seq2 = (const float*)d_in[1];
    const float* ctx  = (const float*)d_in[2];
    const float* Wc1  = (const float*)d_in[3];
    const float* Wc2  = (const float*)d_in[4];
    const float* W1   = (const float*)d_in[5];
    const float* b1   = (const float*)d_in[6];
    const float* W2   = (const float*)d_in[7];
    const float* b2   = (const float*)d_in[8];
    float* out = (float*)d_out;

    __nv_bfloat16 *a1, *a2, *wb1, *wb2, *p1, *p2;
    float *bias1, *bias2, *s1, *s2;
    cudaGetSymbolAddress((void**)&a1, g_a1);
    cudaGetSymbolAddress((void**)&a2, g_a2);
    cudaGetSymbolAddress((void**)&wb1, g_wb1);
    cudaGetSymbolAddress((void**)&wb2, g_wb2);
    cudaGetSymbolAddress((void**)&p1, g_p1);
    cudaGetSymbolAddress((void**)&p2, g_p2);
    cudaGetSymbolAddress((void**)&bias1, g_bias1);
    cudaGetSymbolAddress((void**)&bias2, g_bias2);
    cudaGetSymbolAddress((void**)&s1, g_s1);
    cudaGetSymbolAddress((void**)&s2, g_s2);

    size_t smem = 2 * STAGE_BYTES + 128;
    cudaFuncSetAttribute(gemm_mma_kernel, cudaFuncAttributeMaxDynamicSharedMemorySize, (int)smem);

    zeroctx_kernel<<<256, 256>>>(ctx, Wc1, Wc2, b1, b2, out);
    conv_all_kernel<<<(TOT_F4 + 255) / 256, 256>>>(seq1, seq2, W1, W2);

    dim3 ggrid(MD / 128, AR / 128, 2);   // (8, 64, 2) = 1024 CTAs
    gemm_mma_kernel<<<ggrid, 256, smem>>>(a1, wb1, bias1, p1, s1,
                                          a2, wb2, bias2, p2, s2);

    logits_kernel<<<2048, 256>>>();
    softmax_kernel<<<2, 1024>>>();
    att_kernel<<<dim3(ED / 256, AR / 512, 2), 256>>>(seq1, seq2, out);
}

// round 9
// speedup vs baseline: 1.4160x; 1.0178x over previous
#include <cuda_runtime.h>
#include <cuda_bf16.h>
#include <math.h>
#include <stdint.h>

#define AR 8192
#define ED 1024
#define MD 1024

// ---------------- device scratch ----------------
__device__ __nv_bfloat16 g_a1[(size_t)AR * ED];
__device__ __nv_bfloat16 g_a2[(size_t)AR * ED];
__device__ __nv_bfloat16 g_wb1[(size_t)MD * ED];
__device__ __nv_bfloat16 g_wb2[(size_t)MD * ED];
__device__ __nv_bfloat16 g_p1[(size_t)AR * MD];
__device__ __nv_bfloat16 g_p2[(size_t)AR * MD];
__device__ float g_s1[MD];
__device__ float g_s2[MD];
__device__ float g_bias1[MD];
__device__ float g_bias2[MD];
__device__ float g_logits[2 * AR];
__device__ float g_max[2];
__device__ float g_z[2];

__device__ __forceinline__ float elu1(float x) { return x > 0.0f ? x : expm1f(x); }

// order-preserving float atomic max (standard int/uint trick)
__device__ __forceinline__ void atomicMaxF(float* a, float v) {
    if (v >= 0.0f) atomicMax((int*)a, __float_as_int(v));
    else atomicMin((unsigned int*)a, __float_as_uint(v));
}

__device__ __forceinline__ uint32_t smem_u32(const void* p) {
    uint32_t a;
    asm("{ .reg .u64 t; cvta.to.shared.u64 t, %1; cvt.u32.u64 %0, t; }" : "=r"(a) : "l"(p));
    return a;
}
#define CP_ASYNC16(dst, src) \
    asm volatile("cp.async.cg.shared.global [%0], [%1], 16;" :: "r"(dst), "l"(src))
#define CP_COMMIT() asm volatile("cp.async.commit_group;" ::: "memory")
#define CP_WAIT1()  asm volatile("cp.async.wait_group 1;" ::: "memory")
#define LDMATRIX_X4(r0, r1, r2, r3, addr) \
    asm volatile("ldmatrix.sync.aligned.m8n8.x4.shared.b16 {%0,%1,%2,%3}, [%4];" \
        : "=r"(r0), "=r"(r1), "=r"(r2), "=r"(r3) : "r"(addr))
#define MMA16816(c0, c1, c2, c3, a0, a1, a2, a3, b0, b1) \
    asm volatile("mma.sync.aligned.m16n8k16.row.col.f32.bf16.bf16.f32 " \
        "{%0,%1,%2,%3}, {%4,%5,%6,%7}, {%8,%9}, {%0,%1,%2,%3};" \
        : "+f"(c0), "+f"(c1), "+f"(c2), "+f"(c3) \
        : "r"(a0), "r"(a1), "r"(a2), "r"(a3), "r"(b0), "r"(b1))

// ---------------- merged conv: all 4 tensors f32 -> bf16, 8 f32/thread -----
#define SEQ_F8 (AR * ED / 8)     // 1048576
#define W_F8   (MD * ED / 8)     // 131072
#define TOT_F8 (2 * SEQ_F8 + 2 * W_F8)

__global__ void conv_all_kernel(const float* __restrict__ seq1, const float* __restrict__ seq2,
                                const float* __restrict__ W1, const float* __restrict__ W2) {
    int i = blockIdx.x * blockDim.x + threadIdx.x;
    if (i >= TOT_F8) return;
    const float* src;
    __nv_bfloat16* dst;
    int off;
    if (i < SEQ_F8)                { src = seq1; dst = g_a1;  off = i; }
    else if (i < 2 * SEQ_F8)       { src = seq2; dst = g_a2;  off = i - SEQ_F8; }
    else if (i < 2 * SEQ_F8 + W_F8){ src = W1;   dst = g_wb1; off = i - 2 * SEQ_F8; }
    else                           { src = W2;   dst = g_wb2; off = i - 2 * SEQ_F8 - W_F8; }
    float4 v0 = ((const float4*)src)[2 * off];
    float4 v1 = ((const float4*)src)[2 * off + 1];
    uint4 o;
    asm("cvt.rn.bf16x2.f32 %0, %1, %2;" : "=r"(o.x) : "f"(v0.y), "f"(v0.x));
    asm("cvt.rn.bf16x2.f32 %0, %1, %2;" : "=r"(o.y) : "f"(v0.w), "f"(v0.z));
    asm("cvt.rn.bf16x2.f32 %0, %1, %2;" : "=r"(o.z) : "f"(v1.y), "f"(v1.x));
    asm("cvt.rn.bf16x2.f32 %0, %1, %2;" : "=r"(o.w) : "f"(v1.w), "f"(v1.z));
    ((uint4*)dst)[off] = o;
}

// ---------------- zero + ctx GEMV fused ----------------
__global__ void zeroctx_kernel(const float* __restrict__ ctx,
                               const float* __restrict__ Wc1, const float* __restrict__ Wc2,
                               const float* __restrict__ b1, const float* __restrict__ b2,
                               float* __restrict__ out) {
    int gid = blockIdx.x * blockDim.x + threadIdx.x;
    if (gid < MD) { g_s1[gid] = 0.0f; g_s2[gid] = 0.0f; }
    if (gid < 2 * ED) out[gid] = 0.0f;
    if (gid < 2) { g_max[gid] = -INFINITY; g_z[gid] = 0.0f; }

    int g = gid >> 5;
    int lane = gid & 31;
    int mat = g >> 10, row = g & 1023;
    const float* W = mat ? Wc2 : Wc1;
    const float* b = mat ? b2 : b1;
    float* o = mat ? g_bias2 : g_bias1;
    float acc = 0.0f;
    const float* wr = W + (size_t)row * ED;
    for (int k = lane; k < ED; k += 32) acc += wr[k] * ctx[k];
    #pragma unroll
    for (int off = 16; off > 0; off >>= 1) acc += __shfl_down_sync(0xffffffffu, acc, off);
    if (lane == 0) o[row] = b[row] + acc;
}

// ---------------- bf16 mma.sync GEMM: P = elu(A @ W^T + bias) --------------
#define BK 64
#define NCHUNK (ED / BK)                 // 16
#define STAGE_BYTES (2 * 128 * 128)      // A 16KB + B 16KB

__global__ void __launch_bounds__(256, 2)
gemm_mma_kernel(const __nv_bfloat16* __restrict__ A1, const __nv_bfloat16* __restrict__ B1,
                const float* __restrict__ bias1v, __nv_bfloat16* __restrict__ P1,
                float* __restrict__ S1,
                const __nv_bfloat16* __restrict__ A2, const __nv_bfloat16* __restrict__ B2,
                const float* __restrict__ bias2v, __nv_bfloat16* __restrict__ P2,
                float* __restrict__ S2) {
    extern __shared__ __align__(128) char dyn[];
    __shared__ float bias_s[128];

    const int z = blockIdx.z;
    const __nv_bfloat16* A = z ? A2 : A1;
    const __nv_bfloat16* W = z ? B2 : B1;
    const float* bias = z ? bias2v : bias1v;
    __nv_bfloat16* P = z ? P2 : P1;
    float* S = z ? S2 : S1;

    const int tid = threadIdx.x;
    const int wid = tid >> 5, lane = tid & 31;
    const int rowBlock = blockIdx.y * 128;
    const int colBlock = blockIdx.x * 128;

    uint32_t sbase = (smem_u32(dyn) + 127u) & ~127u;

    if (tid < 128) bias_s[tid] = bias[colBlock + tid];

    const int m0 = (wid & 1) * 64;
    const int n0 = (wid >> 1) * 32;

    float acc[4][4][4];
    #pragma unroll
    for (int i = 0; i < 4; i++)
        #pragma unroll
        for (int j = 0; j < 4; j++)
            #pragma unroll
            for (int q = 0; q < 4; q++) acc[i][j][q] = 0.0f;

    auto load_chunk = [&](int chunk, int stage) {
        const int k0 = chunk * BK;
        uint32_t ab = sbase + stage * STAGE_BYTES;
        uint32_t bb = ab + 16384;
        #pragma unroll
        for (int l = 0; l < 4; l++) {
            int i = tid + l * 256;
            int r = i >> 3, c = i & 7;
            uint32_t dst = ab + (uint32_t)(r * 128) + (uint32_t)((c ^ (r & 7)) << 4);
            CP_ASYNC16(dst, A + (size_t)(rowBlock + r) * ED + k0 + c * 8);
        }
        #pragma unroll
        for (int l = 0; l < 4; l++) {
            int i = tid + l * 256;
            int r = i >> 3, c = i & 7;
            uint32_t dst = bb + (uint32_t)(r * 128) + (uint32_t)((c ^ (r & 7)) << 4);
            CP_ASYNC16(dst, W + (size_t)(colBlock + r) * ED + k0 + c * 8);
        }
        CP_COMMIT();
    };

    load_chunk(0, 0);
    load_chunk(1, 1);

    const int lr = lane & 7, sub = lane >> 3;
    int arow[4], brow[2];
    uint32_t aswz[4], bswz[2];
    #pragma unroll
    for (int mi = 0; mi < 4; mi++) {
        int r = m0 + mi * 16 + ((sub & 1) << 3) + lr;
        arow[mi] = r * 128; aswz[mi] = (uint32_t)(r & 7);
    }
    const uint32_t achunkbit = (uint32_t)(sub >> 1);
    #pragma unroll
    for (int p = 0; p < 2; p++) {
        int r = n0 + p * 16 + ((sub >> 1) << 3) + lr;
        brow[p] = r * 128; bswz[p] = (uint32_t)(r & 7);
    }
    const uint32_t bchunkbit = (uint32_t)(sub & 1);

    for (int ch = 0; ch < NCHUNK; ch++) {
        const int s = ch & 1;
        CP_WAIT1();
        __syncthreads();
        uint32_t ab = sbase + s * STAGE_BYTES;
        uint32_t bb = ab + 16384;

        #pragma unroll
        for (int ks = 0; ks < 4; ks++) {
            uint32_t a[4][4], b[8];
            #pragma unroll
            for (int mi = 0; mi < 4; mi++) {
                uint32_t addr = ab + (uint32_t)arow[mi] +
                                ((((uint32_t)(ks << 1) | achunkbit) ^ aswz[mi]) << 4);
                LDMATRIX_X4(a[mi][0], a[mi][1], a[mi][2], a[mi][3], addr);
            }
            #pragma unroll
            for (int p = 0; p < 2; p++) {
                uint32_t addr = bb + (uint32_t)brow[p] +
                                ((((uint32_t)(ks << 1) | bchunkbit) ^ bswz[p]) << 4);
                LDMATRIX_X4(b[p * 4 + 0], b[p * 4 + 1], b[p * 4 + 2], b[p * 4 + 3], addr);
            }
            #pragma unroll
            for (int mi = 0; mi < 4; mi++)
                #pragma unroll
                for (int nt = 0; nt < 4; nt++)
                    MMA16816(acc[mi][nt][0], acc[mi][nt][1], acc[mi][nt][2], acc[mi][nt][3],
                             a[mi][0], a[mi][1], a[mi][2], a[mi][3],
                             b[nt * 2], b[nt * 2 + 1]);
        }
        __syncthreads();
        if (ch < NCHUNK - 2) load_chunk(ch + 2, s);
        else CP_COMMIT();
    }

    // epilogue: bias + elu -> bf16 stores, fused column sums
    const int qrow = lane >> 2;
    const int qcol = (lane & 3) * 2;
    float csum[4][2];
    #pragma unroll
    for (int nt = 0; nt < 4; nt++) { csum[nt][0] = 0.0f; csum[nt][1] = 0.0f; }

    #pragma unroll
    for (int mi = 0; mi < 4; mi++) {
        #pragma unroll
        for (int nt = 0; nt < 4; nt++) {
            int col = n0 + nt * 8 + qcol;
            float bv0 = bias_s[col], bv1 = bias_s[col + 1];
            int r0 = rowBlock + m0 + mi * 16 + qrow;
            float x0 = elu1(acc[mi][nt][0] + bv0);
            float x1 = elu1(acc[mi][nt][1] + bv1);
            float x2 = elu1(acc[mi][nt][2] + bv0);
            float x3 = elu1(acc[mi][nt][3] + bv1);
            csum[nt][0] += x0 + x2;
            csum[nt][1] += x1 + x3;
            uint32_t p01, p23;
            asm("cvt.rn.bf16x2.f32 %0, %1, %2;" : "=r"(p01) : "f"(x1), "f"(x0));
            asm("cvt.rn.bf16x2.f32 %0, %1, %2;" : "=r"(p23) : "f"(x3), "f"(x2));
            *(uint32_t*)(P + (size_t)r0 * MD + colBlock + col) = p01;
            *(uint32_t*)(P + (size_t)(r0 + 8) * MD + colBlock + col) = p23;
        }
    }
    #pragma unroll
    for (int nt = 0; nt < 4; nt++) {
        #pragma unroll
        for (int q = 0; q < 2; q++) {
            float v = csum[nt][q];
            v += __shfl_xor_sync(0xffffffffu, v, 4);
            v += __shfl_xor_sync(0xffffffffu, v, 8);
            v += __shfl_xor_sync(0xffffffffu, v, 16);
            if (lane < 4) atomicAdd(&S[colBlock + n0 + nt * 8 + qcol + q], v);
        }
    }
}

// ---------------- logits GEMV + block max -> atomic ----------------
__global__ void logits_kernel() {
    __shared__ float s[MD];
    __shared__ float wmax[8];
    int mat = blockIdx.x >> 10;
    const uint4* P = (const uint4*)(mat ? g_p2 : g_p1);
    const float* S = mat ? g_s1 : g_s2;
    float* L = g_logits + mat * AR;

    for (int i = threadIdx.x; i < MD; i += blockDim.x) s[i] = S[i];
    __syncthreads();

    int wid = threadIdx.x >> 5, lane = threadIdx.x & 31;
    int row = (blockIdx.x & 1023) * 8 + wid;
    const uint4* p = P + (size_t)row * 128;   // 128 uint4 per row
    float acc = 0.0f;
    #pragma unroll
    for (int i = 0; i < 4; i++) {
        int j = i * 32 + lane;
        uint4 u = p[j];
        float4 sv0 = *(const float4*)&s[8 * j];
        float4 sv1 = *(const float4*)&s[8 * j + 4];
        __nv_bfloat162 h0 = *(__nv_bfloat162*)&u.x;
        __nv_bfloat162 h1 = *(__nv_bfloat162*)&u.y;
        __nv_bfloat162 h2 = *(__nv_bfloat162*)&u.z;
        __nv_bfloat162 h3 = *(__nv_bfloat162*)&u.w;
        acc += __bfloat162float(h0.x) * sv0.x + __bfloat162float(h0.y) * sv0.y;
        acc += __bfloat162float(h1.x) * sv0.z + __bfloat162float(h1.y) * sv0.w;
        acc += __bfloat162float(h2.x) * sv1.x + __bfloat162float(h2.y) * sv1.y;
        acc += __bfloat162float(h3.x) * sv1.z + __bfloat162float(h3.y) * sv1.w;
    }
    #pragma unroll
    for (int o = 16; o > 0; o >>= 1) acc += __shfl_down_sync(0xffffffffu, acc, o);
    if (lane == 0) { L[row] = acc; wmax[wid] = acc; }
    __syncthreads();
    if (threadIdx.x == 0) {
        float m = wmax[0];
        #pragma unroll
        for (int i = 1; i < 8; i++) m = fmaxf(m, wmax[i]);
        atomicMaxF(&g_max[mat], m);
    }
}

// ---------------- Z = sum exp(L - m) ----------------
__global__ void zsum_kernel() {
    __shared__ float wsum[32];
    int mat = blockIdx.y;
    float m = g_max[mat];
    int i = blockIdx.x * 1024 + threadIdx.x;
    float e = expf(g_logits[mat * AR + i] - m);
    #pragma unroll
    for (int o = 16; o > 0; o >>= 1) e += __shfl_down_sync(0xffffffffu, e, o);
    int wid = threadIdx.x >> 5, lane = threadIdx.x & 31;
    if (lane == 0) wsum[wid] = e;
    __syncthreads();
    if (wid == 0) {
        float v = wsum[lane];
        #pragma unroll
        for (int o = 16; o > 0; o >>= 1) v += __shfl_down_sync(0xffffffffu, v, o);
        if (lane == 0) atomicAdd(&g_z[mat], v);
    }
}

// ---------------- att = seq.T @ softmax(L), weights computed inline --------
__global__ void att_kernel(const float* __restrict__ seq1, const float* __restrict__ seq2,
                           float* __restrict__ out) {
    __shared__ float ws[512];
    int mat = blockIdx.z;
    const float* Sq = mat ? seq2 : seq1;
    const float* L = g_logits + mat * AR;
    int c = blockIdx.x * 256 + threadIdx.x;
    int r0 = blockIdx.y * 512;

    float m = g_max[mat];
    float invz = 1.0f / g_z[mat];
    for (int i = threadIdx.x; i < 512; i += 256)
        ws[i] = expf(L[r0 + i] - m) * invz;
    __syncthreads();

    float acc0 = 0.0f, acc1 = 0.0f;
    #pragma unroll 4
    for (int i = 0; i < 512; i += 2) {
        acc0 += Sq[(size_t)(r0 + i) * ED + c] * ws[i];
        acc1 += Sq[(size_t)(r0 + i + 1) * ED + c] * ws[i + 1];
    }
    atomicAdd(&out[mat * ED + c], acc0 + acc1);
}

// ---------------- launch ----------------
extern "C" void kernel_launch(void* const* d_in, const int* in_sizes, int n_in,
                              void* d_out, int out_size) {
    const float* seq1 = (const float*)d_in[0];
    const float* seq2 = (const float*)d_in[1];
    const float* ctx  = (const float*)d_in[2];
    const float* Wc1  = (const float*)d_in[3];
    const float* Wc2  = (const float*)d_in[4];
    const float* W1   = (const float*)d_in[5];
    const float* b1   = (const float*)d_in[6];
    const float* W2   = (const float*)d_in[7];
    const float* b2   = (const float*)d_in[8];
    float* out = (float*)d_out;

    __nv_bfloat16 *a1, *a2, *wb1, *wb2, *p1, *p2;
    float *bias1, *bias2, *s1, *s2;
    cudaGetSymbolAddress((void**)&a1, g_a1);
    cudaGetSymbolAddress((void**)&a2, g_a2);
    cudaGetSymbolAddress((void**)&wb1, g_wb1);
    cudaGetSymbolAddress((void**)&wb2, g_wb2);
    cudaGetSymbolAddress((void**)&p1, g_p1);
    cudaGetSymbolAddress((void**)&p2, g_p2);
    cudaGetSymbolAddress((void**)&bias1, g_bias1);
    cudaGetSymbolAddress((void**)&bias2, g_bias2);
    cudaGetSymbolAddress((void**)&s1, g_s1);
    cudaGetSymbolAddress((void**)&s2, g_s2);

    size_t smem = 2 * STAGE_BYTES + 128;
    cudaFuncSetAttribute(gemm_mma_kernel, cudaFuncAttributeMaxDynamicSharedMemorySize, (int)smem);

    zeroctx_kernel<<<256, 256>>>(ctx, Wc1, Wc2, b1, b2, out);
    conv_all_kernel<<<(TOT_F8 + 255) / 256, 256>>>(seq1, seq2, W1, W2);

    dim3 ggrid(MD / 128, AR / 128, 2);   // 1024 CTAs
    gemm_mma_kernel<<<ggrid, 256, smem>>>(a1, wb1, bias1, p1, s1,
                                          a2, wb2, bias2, p2, s2);

    logits_kernel<<<2048, 256>>>();
    zsum_kernel<<<dim3(8, 2), 1024>>>();
    att_kernel<<<dim3(ED / 256, AR / 512, 2), 256>>>(seq1, seq2, out);
}